// round 1
// baseline (speedup 1.0000x reference)
#include <cuda_runtime.h>
#include <cuda_bf16.h>
#include <math.h>

// Problem constants (fixed by the dataset)
#define E      256
#define H1     32
#define H2     16
#define MAXD   1024
#define MAXN   (1024*100)

// ---------------- device scratch (no allocations allowed) ----------------
__device__ float    g_logits[MAXN];
__device__ int      g_dagids[MAXN];
__device__ int      g_offsets[MAXD + 1];
__device__ float    g_yop[MAXD * H1];   // y @ opW1_y  per dag
__device__ float    g_ypr[MAXD * H1];   // y @ prW1_y  per dag
__device__ float    g_czop[H1];         // z @ opW1_z + op_b1
__device__ float    g_czpr[H1];         // z @ prW1_z + pr_b1
__device__ unsigned g_gmax;             // encoded float max
__device__ float    g_partials[256];

// ordered-float <-> unsigned monotonic encoding (atomicMax-able)
__device__ __forceinline__ unsigned fenc(float f) {
    unsigned u = __float_as_uint(f);
    return (u & 0x80000000u) ? ~u : (u | 0x80000000u);
}
__device__ __forceinline__ float fdec(unsigned u) {
    return (u & 0x80000000u) ? __uint_as_float(u ^ 0x80000000u)
                             : __uint_as_float(~u);
}

// ---------------- K0: scan num_ops -> offsets; z-part constants ----------------
__global__ void k_setup(const int* __restrict__ num_ops, int D,
                        const float* __restrict__ z,
                        const float* __restrict__ opW1, const float* __restrict__ opb1,
                        const float* __restrict__ prW1, const float* __restrict__ prb1)
{
    __shared__ int s[1024];
    int t = threadIdx.x;
    s[t] = (t < D) ? num_ops[t] : 0;
    __syncthreads();
    // Hillis-Steele inclusive scan over 1024
    #pragma unroll
    for (int off = 1; off < 1024; off <<= 1) {
        int v = (t >= off) ? s[t - off] : 0;
        __syncthreads();
        s[t] += v;
        __syncthreads();
    }
    if (t == 0) { g_offsets[0] = 0; g_gmax = 0u; }
    if (t < D) g_offsets[t + 1] = s[t];

    if (t < H1) {
        float a = opb1[t];
        #pragma unroll 4
        for (int k = 0; k < E; k++) a += z[k] * opW1[(2 * E + k) * H1 + t];
        g_czop[t] = a;
    } else if (t < 2 * H1) {
        int j = t - H1;
        float a = prb1[j];
        #pragma unroll 4
        for (int k = 0; k < E; k++) a += z[k] * prW1[(1 + E + k) * H1 + j];
        g_czpr[j] = a;
    }
}

// ---------------- K1: fill dag ids ----------------
__global__ void k_dagfill()
{
    int d = blockIdx.x;
    int s = g_offsets[d], e = g_offsets[d + 1];
    for (int i = s + threadIdx.x; i < e; i += blockDim.x) g_dagids[i] = d;
}

// ---------------- K2: per-dag y @ W1_y for both branches ----------------
__global__ void k_ydag(const float* __restrict__ y,
                       const float* __restrict__ opW1,
                       const float* __restrict__ prW1)
{
    __shared__ float sy[E];
    int d = blockIdx.x, t = threadIdx.x;
    for (int k = t; k < E; k += 64) sy[k] = y[(size_t)d * E + k];
    __syncthreads();
    if (t < H1) {
        float a = 0.f;
        #pragma unroll 4
        for (int k = 0; k < E; k++) a += sy[k] * opW1[(E + k) * H1 + t];
        g_yop[d * H1 + t] = a;
    } else {
        int j = t - H1;
        float a = 0.f;
        #pragma unroll 4
        for (int k = 0; k < E; k++) a += sy[k] * prW1[(1 + k) * H1 + j];
        g_ypr[d * H1 + j] = a;
    }
}

// ---------------- K3: main op-branch MLP + global max ----------------
__global__ void __launch_bounds__(256)
k_op(const float* __restrict__ x,
     const float* __restrict__ opW1, const float* __restrict__ opW2,
     const float* __restrict__ opb2, const float* __restrict__ opW3,
     const float* __restrict__ opb3, const float* __restrict__ msk, int n)
{
    __shared__ float sW1[E * H1];   // 32 KB, x-part rows of W1
    __shared__ float sW2[H1 * H2];
    __shared__ float sW3[H2];
    __shared__ float sb2[H2];
    __shared__ float sH[8][4 * 33]; // per-warp h1 transpose, padded
    __shared__ float sMax[8];

    int tid = threadIdx.x;
    for (int i = tid; i < E * H1; i += 256) sW1[i] = opW1[i];
    for (int i = tid; i < H1 * H2; i += 256) sW2[i] = opW2[i];
    if (tid < H2) { sW3[tid] = opW3[tid]; sb2[tid] = opb2[tid]; }
    __syncthreads();

    int warp = tid >> 5, lane = tid & 31;
    int base = (blockIdx.x * 8 + warp) * 4;

    float acc0, acc1, acc2, acc3;
    const float4 *xp0, *xp1, *xp2, *xp3;
    {
        int i0 = min(base + 0, n - 1), i1 = min(base + 1, n - 1);
        int i2 = min(base + 2, n - 1), i3 = min(base + 3, n - 1);
        float cz = g_czop[lane];
        acc0 = g_yop[g_dagids[i0] * H1 + lane] + cz;
        acc1 = g_yop[g_dagids[i1] * H1 + lane] + cz;
        acc2 = g_yop[g_dagids[i2] * H1 + lane] + cz;
        acc3 = g_yop[g_dagids[i3] * H1 + lane] + cz;
        xp0 = reinterpret_cast<const float4*>(x) + (size_t)i0 * (E / 4);
        xp1 = reinterpret_cast<const float4*>(x) + (size_t)i1 * (E / 4);
        xp2 = reinterpret_cast<const float4*>(x) + (size_t)i2 * (E / 4);
        xp3 = reinterpret_cast<const float4*>(x) + (size_t)i3 * (E / 4);
    }

    #pragma unroll 4
    for (int k4 = 0; k4 < E / 4; k4++) {
        float4 a = __ldg(xp0 + k4);
        float4 b = __ldg(xp1 + k4);
        float4 c = __ldg(xp2 + k4);
        float4 d = __ldg(xp3 + k4);
        float w0 = sW1[(k4 * 4 + 0) * H1 + lane];
        float w1 = sW1[(k4 * 4 + 1) * H1 + lane];
        float w2 = sW1[(k4 * 4 + 2) * H1 + lane];
        float w3 = sW1[(k4 * 4 + 3) * H1 + lane];
        acc0 = fmaf(a.x, w0, fmaf(a.y, w1, fmaf(a.z, w2, fmaf(a.w, w3, acc0))));
        acc1 = fmaf(b.x, w0, fmaf(b.y, w1, fmaf(b.z, w2, fmaf(b.w, w3, acc1))));
        acc2 = fmaf(c.x, w0, fmaf(c.y, w1, fmaf(c.z, w2, fmaf(c.w, w3, acc2))));
        acc3 = fmaf(d.x, w0, fmaf(d.y, w1, fmaf(d.z, w2, fmaf(d.w, w3, acc3))));
    }

    sH[warp][0 * 33 + lane] = fmaxf(acc0, 0.f);
    sH[warp][1 * 33 + lane] = fmaxf(acc1, 0.f);
    sH[warp][2 * 33 + lane] = fmaxf(acc2, 0.f);
    sH[warp][3 * 33 + lane] = fmaxf(acc3, 0.f);
    __syncwarp();

    // layers 2+3: lane = (op o = lane>>3, neuron pair m = lane&7)
    int o = lane >> 3, m = lane & 7;
    float h2a = sb2[m], h2b = sb2[m + 8];
    #pragma unroll
    for (int j = 0; j < H1; j++) {
        float h = sH[warp][o * 33 + j];
        h2a += h * sW2[j * H2 + m];
        h2b += h * sW2[j * H2 + m + 8];
    }
    float part = fmaxf(h2a, 0.f) * sW3[m] + fmaxf(h2b, 0.f) * sW3[m + 8];
    part += __shfl_xor_sync(0xffffffffu, part, 1);
    part += __shfl_xor_sync(0xffffffffu, part, 2);
    part += __shfl_xor_sync(0xffffffffu, part, 4);

    float lg = -INFINITY;
    if (m == 0) {
        int i = base + o;
        if (i < n) {
            lg = part + opb3[0] - (1.f - msk[i]) * 1000.f;
            g_logits[i] = lg;
        }
    }
    // warp max over the 4 writer lanes (others are -inf)
    lg = fmaxf(lg, __shfl_xor_sync(0xffffffffu, lg, 8));
    lg = fmaxf(lg, __shfl_xor_sync(0xffffffffu, lg, 16));
    if (lane == 0) sMax[warp] = lg;
    __syncthreads();
    if (tid == 0) {
        float bm = sMax[0];
        #pragma unroll
        for (int w = 1; w < 8; w++) bm = fmaxf(bm, sMax[w]);
        atomicMax(&g_gmax, fenc(bm));
    }
}

// ---------------- K4: exp + fixed-grid partial sums ----------------
__global__ void __launch_bounds__(256)
k_exp(float* __restrict__ out_ops, int n)
{
    __shared__ float red[256];
    float gmax = fdec(g_gmax);
    float s = 0.f;
    for (int i = blockIdx.x * 256 + threadIdx.x; i < n; i += 256 * 256) {
        float e = expf(g_logits[i] - gmax);
        out_ops[i] = e;
        s += e;
    }
    red[threadIdx.x] = s;
    __syncthreads();
    for (int st = 128; st > 0; st >>= 1) {
        if (threadIdx.x < st) red[threadIdx.x] += red[threadIdx.x + st];
        __syncthreads();
    }
    if (threadIdx.x == 0) g_partials[blockIdx.x] = red[0];
}

// ---------------- K5: reduce partials (redundantly per block) + normalize ----------------
__global__ void __launch_bounds__(256)
k_norm(float* __restrict__ out_ops, int n)
{
    __shared__ float red[256];
    red[threadIdx.x] = g_partials[threadIdx.x];
    __syncthreads();
    for (int st = 128; st > 0; st >>= 1) {
        if (threadIdx.x < st) red[threadIdx.x] += red[threadIdx.x + st];
        __syncthreads();
    }
    float inv = 1.f / red[0];
    for (int i = blockIdx.x * 256 + threadIdx.x; i < n; i += 256 * 256)
        out_ops[i] *= inv;
}

// ---------------- K6: full prlvl branch, one block per dag ----------------
__global__ void k_prlvl(const float* __restrict__ prW1,
                        const float* __restrict__ prW2,
                        const float* __restrict__ prb2,
                        const float* __restrict__ prW3,
                        const float* __restrict__ prb3,
                        const float* __restrict__ pmsk,
                        float* __restrict__ out_pr, int W)
{
    __shared__ float syp[H1], sr0[H1], sW2[H1 * H2], sW3[H2], sb2[H2];
    __shared__ float red[128];
    int d = blockIdx.x, t = threadIdx.x;
    if (t < H1) {
        syp[t] = g_ypr[d * H1 + t] + g_czpr[t];
        sr0[t] = prW1[t];               // row 0 of pr_W1 (limit weights)
    }
    for (int i = t; i < H1 * H2; i += blockDim.x) sW2[i] = prW2[i];
    if (t < H2) { sW3[t] = prW3[t]; sb2[t] = prb2[t]; }
    __syncthreads();

    float limit = (float)(t + 1);
    float h1[H1];
    #pragma unroll
    for (int j = 0; j < H1; j++) h1[j] = fmaxf(syp[j] + limit * sr0[j], 0.f);

    float lg = prb3[0];
    #pragma unroll
    for (int m = 0; m < H2; m++) {
        float h2 = sb2[m];
        #pragma unroll
        for (int j = 0; j < H1; j++) h2 += h1[j] * sW2[j * H2 + m];
        lg += fmaxf(h2, 0.f) * sW3[m];
    }
    lg -= (1.f - pmsk[(size_t)d * W + t]) * 1000.f;

    // softmax over W workers within the block
    red[t] = lg;
    __syncthreads();
    for (int st = blockDim.x >> 1; st > 0; st >>= 1) {
        if (t < st) red[t] = fmaxf(red[t], red[t + st]);
        __syncthreads();
    }
    float mx = red[0];
    __syncthreads();
    float e = expf(lg - mx);
    red[t] = e;
    __syncthreads();
    for (int st = blockDim.x >> 1; st > 0; st >>= 1) {
        if (t < st) red[t] += red[t + st];
        __syncthreads();
    }
    out_pr[(size_t)d * W + t] = e / red[0];
}

// ---------------- launch ----------------
extern "C" void kernel_launch(void* const* d_in, const int* in_sizes, int n_in,
                              void* d_out, int out_size)
{
    // anchor on x (the only input of size N*E); tolerates scalar inputs
    int ix = -1;
    for (int i = 0; i < n_in; i++) {
        if (in_sizes[i] == MAXN * E) { ix = i; break; }
    }
    if (ix < 0) return;

    const int*   num_ops = (const int*)d_in[0];
    int D = in_sizes[0];
    const float* x    = (const float*)d_in[ix + 0];
    const float* y    = (const float*)d_in[ix + 1];
    const float* z    = (const float*)d_in[ix + 2];
    const float* omsk = (const float*)d_in[ix + 3];
    const float* pmsk = (const float*)d_in[ix + 4];
    const float* opW1 = (const float*)d_in[ix + 5];
    const float* opb1 = (const float*)d_in[ix + 6];
    const float* opW2 = (const float*)d_in[ix + 7];
    const float* opb2 = (const float*)d_in[ix + 8];
    const float* opW3 = (const float*)d_in[ix + 9];
    const float* opb3 = (const float*)d_in[ix + 10];
    const float* prW1 = (const float*)d_in[ix + 11];
    const float* prb1 = (const float*)d_in[ix + 12];
    const float* prW2 = (const float*)d_in[ix + 13];
    const float* prb2 = (const float*)d_in[ix + 14];
    const float* prW3 = (const float*)d_in[ix + 15];
    const float* prb3 = (const float*)d_in[ix + 16];

    int n = in_sizes[ix] / E;                       // 102400
    int W = in_sizes[ix + 4] / D;                   // 64
    float* out = (float*)d_out;
    float* out_ops = out;
    float* out_pr  = out + n;
    (void)out_size;

    k_setup<<<1, 1024>>>(num_ops, D, z, opW1, opb1, prW1, prb1);
    k_dagfill<<<D, 128>>>();
    k_ydag<<<D, 64>>>(y, opW1, prW1);
    k_op<<<(n + 31) / 32, 256>>>(x, opW1, opW2, opb2, opW3, opb3, omsk, n);
    k_exp<<<256, 256>>>(out_ops, n);
    k_norm<<<256, 256>>>(out_ops, n);
    k_prlvl<<<D, W>>>(prW1, prW2, prb2, prW3, prb3, pmsk, out_pr, W);
}

// round 4
// speedup vs baseline: 1.4642x; 1.4642x over previous
#include <cuda_runtime.h>
#include <cuda_bf16.h>
#include <math.h>

#define E      256
#define H1     32
#define H2     16
#define MAXD   1024
#define MAXN   (1024*100)

typedef unsigned long long ull;

// ---------------- device scratch ----------------
__device__ float    g_logits[MAXN];
__device__ int      g_dagids[MAXN];
__device__ int      g_offsets[MAXD + 1];
__device__ float    g_yop[MAXD * H1];
__device__ float    g_ypr[MAXD * H1];
__device__ float    g_czop[H1];
__device__ float    g_czpr[H1];
__device__ unsigned g_gmax;
__device__ float    g_partials[256];

__device__ __forceinline__ unsigned fenc(float f) {
    unsigned u = __float_as_uint(f);
    return (u & 0x80000000u) ? ~u : (u | 0x80000000u);
}
__device__ __forceinline__ float fdec(unsigned u) {
    return (u & 0x80000000u) ? __uint_as_float(u ^ 0x80000000u)
                             : __uint_as_float(~u);
}
__device__ __forceinline__ ull ffma2(ull a, ull b, ull c) {
    ull d;
    asm("fma.rn.f32x2 %0, %1, %2, %3;" : "=l"(d) : "l"(a), "l"(b), "l"(c));
    return d;
}
__device__ __forceinline__ ull pack2(float lo, float hi) {
    return (ull)__float_as_uint(lo) | ((ull)__float_as_uint(hi) << 32);
}
__device__ __forceinline__ float unpack_sum(ull v) {
    return __uint_as_float((unsigned)(v & 0xffffffffu)) +
           __uint_as_float((unsigned)(v >> 32));
}

// ---------------- K0: scan num_ops -> offsets; z-part constants ----------------
__global__ void k_scan(const int* __restrict__ num_ops, int D,
                       const float* __restrict__ z,
                       const float* __restrict__ opW1, const float* __restrict__ opb1,
                       const float* __restrict__ prW1, const float* __restrict__ prb1)
{
    __shared__ int   s[1024];
    __shared__ float sred[1024];
    int t = threadIdx.x;
    s[t] = (t < D) ? num_ops[t] : 0;
    __syncthreads();
    #pragma unroll
    for (int off = 1; off < 1024; off <<= 1) {
        int v = (t >= off) ? s[t - off] : 0;
        __syncthreads();
        s[t] += v;
        __syncthreads();
    }
    if (t == 0) { g_offsets[0] = 0; g_gmax = 0u; }
    if (t < D) g_offsets[t + 1] = s[t];

    // cz for both branches, parallel over k-chunks
    {
        int j = t & 31;
        int c = (t >> 5) & 15;       // 16 chunks of 16 k's
        float a = 0.f;
        if (t < 512) {
            #pragma unroll
            for (int kk = 0; kk < 16; kk++) {
                int k = c * 16 + kk;
                a += z[k] * opW1[(2 * E + k) * H1 + j];
            }
        } else {
            #pragma unroll
            for (int kk = 0; kk < 16; kk++) {
                int k = c * 16 + kk;
                a += z[k] * prW1[(1 + E + k) * H1 + j];
            }
        }
        sred[t] = a;
    }
    __syncthreads();
    if (t < 32) {
        float a = opb1[t];
        #pragma unroll
        for (int c = 0; c < 16; c++) a += sred[t + 32 * c];
        g_czop[t] = a;
    } else if (t >= 512 && t < 544) {
        int j = t - 512;
        float a = prb1[j];
        #pragma unroll
        for (int c = 0; c < 16; c++) a += sred[512 + j + 32 * c];
        g_czpr[j] = a;
    }
}

// ---------------- K1: precompute y@W1y (both branches) + dagfill ----------------
#define PRE_SMEM (32768 + 32768 + 16384)
__global__ void __launch_bounds__(256)
k_pre(const float* __restrict__ y,
      const float* __restrict__ opW1,
      const float* __restrict__ prW1, int D)
{
    extern __shared__ unsigned char sm_raw[];
    int nb = D / 16;
    if (blockIdx.x >= nb) {
        // dagfill
        int d0 = (blockIdx.x - nb) * 16;
        for (int d = d0; d < d0 + 16; d++) {
            int s = g_offsets[d], e = g_offsets[d + 1];
            for (int i = s + threadIdx.x; i < e; i += 256) g_dagids[i] = d;
        }
        return;
    }
    ull* swop = (ull*)sm_raw;                    // [128][32] pairs, op y-part
    ull* swpr = (ull*)(sm_raw + 32768);          // [128][32] pairs, pr y-part
    ull* syu  = (ull*)(sm_raw + 65536);          // [16][128] y rows as pairs

    int tid = threadIdx.x;
    int d0 = blockIdx.x * 16;

    for (int idx = tid; idx < 128 * 32; idx += 256) {
        int k2 = idx >> 5, j = idx & 31;
        swop[idx] = pack2(opW1[(E + 2 * k2) * H1 + j],
                          opW1[(E + 2 * k2 + 1) * H1 + j]);
        swpr[idx] = pack2(prW1[(1 + 2 * k2) * H1 + j],
                          prW1[(1 + 2 * k2 + 1) * H1 + j]);
    }
    {
        const float4* ysrc = (const float4*)(y + (size_t)d0 * E);
        float4* ydst = (float4*)syu;
        for (int idx = tid; idx < 16 * E / 4; idx += 256) ydst[idx] = ysrc[idx];
    }
    __syncthreads();

    int warp = tid >> 5, lane = tid & 31;
    for (int slot = warp; slot < 32; slot += 8) {
        int dag = slot & 15, br = slot >> 4;
        const ull* w = br ? swpr : swop;
        const ull* xr = syu + dag * 128;
        ull acc = 0;
        #pragma unroll 16
        for (int k2 = 0; k2 < 128; k2++)
            acc = ffma2(xr[k2], w[k2 * 32 + lane], acc);
        float v = unpack_sum(acc);
        if (br) g_ypr[(d0 + dag) * H1 + lane] = v;
        else    g_yop[(d0 + dag) * H1 + lane] = v;
    }
}

// ---------------- K2: main op-branch MLP + global max ----------------
#define OP_SMEM_SXU   0                       // 64*128 ull = 65536
#define OP_SMEM_SWP   65536                   // 128*32 ull = 32768
#define OP_SMEM_SW2   98304                   // 512 f = 2048
#define OP_SMEM_SW3   100352                  // 16 f
#define OP_SMEM_SB2   100416                  // 16 f
#define OP_SMEM_SH    100480                  // 8*8*33 f = 8448
#define OP_SMEM_SMAX  108928                  // 8 f
#define OP_SMEM_TOTAL 109056
__global__ void __launch_bounds__(256)
k_op(const float* __restrict__ x,
     const float* __restrict__ opW1, const float* __restrict__ opW2,
     const float* __restrict__ opb2, const float* __restrict__ opW3,
     const float* __restrict__ opb3, const float* __restrict__ msk, int n)
{
    extern __shared__ unsigned char sm_raw[];
    ull*   sxu  = (ull*)(sm_raw + OP_SMEM_SXU);
    ull*   swp  = (ull*)(sm_raw + OP_SMEM_SWP);
    float* sW2  = (float*)(sm_raw + OP_SMEM_SW2);
    float* sW3  = (float*)(sm_raw + OP_SMEM_SW3);
    float* sb2  = (float*)(sm_raw + OP_SMEM_SB2);
    float* sH   = (float*)(sm_raw + OP_SMEM_SH);
    float* sMax = (float*)(sm_raw + OP_SMEM_SMAX);

    int tid = threadIdx.x;
    int base_op = blockIdx.x * 64;

    // stage x tile: 64 rows x 256 f, coalesced float4
    {
        const float4* src = (const float4*)(x + (size_t)base_op * E);
        float4* dst = (float4*)sxu;
        int lim = 64 * E / 4;   // 4096
        if (base_op + 64 <= n) {
            #pragma unroll 4
            for (int idx = tid; idx < lim; idx += 256) dst[idx] = src[idx];
        } else {
            for (int idx = tid; idx < lim; idx += 256) {
                int row = idx >> 6;
                int gi = min(base_op + row, n - 1);
                dst[idx] = ((const float4*)(x + (size_t)gi * E))[idx & 63];
            }
        }
    }
    // stage W1 x-part as (k,k+1) pairs
    for (int idx = tid; idx < 128 * 32; idx += 256) {
        int k2 = idx >> 5, j = idx & 31;
        swp[idx] = pack2(opW1[(2 * k2) * H1 + j], opW1[(2 * k2 + 1) * H1 + j]);
    }
    for (int i = tid; i < H1 * H2; i += 256) sW2[i] = opW2[i];
    if (tid < H2) { sW3[tid] = opW3[tid]; sb2[tid] = opb2[tid]; }
    __syncthreads();

    int warp = tid >> 5, lane = tid & 31;

    // init accumulators: lo half = y-part + z-part const, hi = 0
    ull acc[8];
    {
        float cz = g_czop[lane];
        #pragma unroll
        for (int u = 0; u < 8; u++) {
            int i = min(base_op + warp * 8 + u, n - 1);
            acc[u] = pack2(g_yop[g_dagids[i] * H1 + lane] + cz, 0.f);
        }
    }

    const ull* xb = sxu + (warp * 8) * 128;
    #pragma unroll 16
    for (int k2 = 0; k2 < 128; k2++) {
        ull w = swp[k2 * 32 + lane];
        #pragma unroll
        for (int u = 0; u < 8; u++)
            acc[u] = ffma2(xb[u * 128 + k2], w, acc[u]);
    }

    float* sHw = sH + warp * (8 * 33);
    #pragma unroll
    for (int u = 0; u < 8; u++)
        sHw[u * 33 + lane] = fmaxf(unpack_sum(acc[u]), 0.f);
    __syncwarp();

    // layers 2+3: lane -> (op o = lane>>2, neuron group m = lane&3)
    int o = lane >> 2, m = lane & 3;
    float h2[4];
    #pragma unroll
    for (int q = 0; q < 4; q++) h2[q] = sb2[m + 4 * q];
    const float* hrow = sHw + o * 33;
    #pragma unroll
    for (int j = 0; j < H1; j++) {
        float h = hrow[j];
        #pragma unroll
        for (int q = 0; q < 4; q++) h2[q] += h * sW2[j * H2 + m + 4 * q];
    }
    float part = 0.f;
    #pragma unroll
    for (int q = 0; q < 4; q++) part += fmaxf(h2[q], 0.f) * sW3[m + 4 * q];
    part += __shfl_xor_sync(0xffffffffu, part, 1);
    part += __shfl_xor_sync(0xffffffffu, part, 2);

    float lg = -INFINITY;
    if (m == 0) {
        int i = base_op + warp * 8 + o;
        if (i < n) {
            lg = part + opb3[0] - (1.f - msk[i]) * 1000.f;
            g_logits[i] = lg;
        }
    }
    lg = fmaxf(lg, __shfl_xor_sync(0xffffffffu, lg, 4));
    lg = fmaxf(lg, __shfl_xor_sync(0xffffffffu, lg, 8));
    lg = fmaxf(lg, __shfl_xor_sync(0xffffffffu, lg, 16));
    if (lane == 0) sMax[warp] = lg;
    __syncthreads();
    if (tid == 0) {
        float bm = sMax[0];
        #pragma unroll
        for (int w = 1; w < 8; w++) bm = fmaxf(bm, sMax[w]);
        atomicMax(&g_gmax, fenc(bm));
    }
}

// ---------------- K3: exp + partial sums (blocks<256) ; prlvl (blocks>=256) ----------------
__global__ void __launch_bounds__(256)
k_exp_prlvl(float* __restrict__ out_ops, int n,
            const float* __restrict__ prW1,
            const float* __restrict__ prW2,
            const float* __restrict__ prb2,
            const float* __restrict__ prW3,
            const float* __restrict__ prb3,
            const float* __restrict__ pmsk,
            float* __restrict__ out_pr, int W)
{
    int t = threadIdx.x;
    if (blockIdx.x < 256) {
        __shared__ float red[256];
        float gmax = fdec(g_gmax);
        float s = 0.f;
        for (int i = blockIdx.x * 256 + t; i < n; i += 256 * 256) {
            float e = expf(g_logits[i] - gmax);
            out_ops[i] = e;
            s += e;
        }
        red[t] = s;
        __syncthreads();
        for (int st = 128; st > 0; st >>= 1) {
            if (t < st) red[t] += red[t + st];
            __syncthreads();
        }
        if (t == 0) g_partials[blockIdx.x] = red[0];
        return;
    }
    // ---- prlvl: 4 dags per block (W = 64) ----
    __shared__ float sYP[4][H1];
    __shared__ float sr0[H1];
    __shared__ float sW2[H1 * H2];
    __shared__ float sW3[H2], sb2[H2];
    __shared__ float red[4][64];

    int d0 = (blockIdx.x - 256) * 4;
    int g = t >> 6, wk = t & 63;
    int dag = d0 + g;

    if (t < 128) {                     // FIXED: one write per (dag,neuron)
        int gg = t >> 5, j = t & 31;   // gg in {0,1,2,3}
        sYP[gg][j] = g_ypr[(d0 + gg) * H1 + j] + g_czpr[j];
    }
    if (t < H1) sr0[t] = prW1[t];
    for (int i = t; i < H1 * H2; i += 256) sW2[i] = prW2[i];
    if (t < H2) { sW3[t] = prW3[t]; sb2[t] = prb2[t]; }
    __syncthreads();

    float limit = (float)(wk + 1);
    float h1[H1];
    #pragma unroll
    for (int j = 0; j < H1; j++)
        h1[j] = fmaxf(sYP[g][j] + limit * sr0[j], 0.f);

    float lg = prb3[0];
    #pragma unroll 4
    for (int m = 0; m < H2; m++) {
        float v = sb2[m];
        #pragma unroll
        for (int j = 0; j < H1; j++) v += h1[j] * sW2[j * H2 + m];
        lg += fmaxf(v, 0.f) * sW3[m];
    }
    lg -= (1.f - pmsk[(size_t)dag * W + wk]) * 1000.f;

    red[g][wk] = lg;
    __syncthreads();
    for (int st = 32; st > 0; st >>= 1) {
        if (wk < st) red[g][wk] = fmaxf(red[g][wk], red[g][wk + st]);
        __syncthreads();
    }
    float mx = red[g][0];
    __syncthreads();
    float e = expf(lg - mx);
    red[g][wk] = e;
    __syncthreads();
    for (int st = 32; st > 0; st >>= 1) {
        if (wk < st) red[g][wk] += red[g][wk + st];
        __syncthreads();
    }
    out_pr[(size_t)dag * W + wk] = e / red[g][0];
}

// ---------------- K4: reduce partials + normalize ----------------
__global__ void __launch_bounds__(256)
k_norm(float* __restrict__ out_ops, int n)
{
    __shared__ float red[256];
    red[threadIdx.x] = g_partials[threadIdx.x];
    __syncthreads();
    for (int st = 128; st > 0; st >>= 1) {
        if (threadIdx.x < st) red[threadIdx.x] += red[threadIdx.x + st];
        __syncthreads();
    }
    float inv = 1.f / red[0];
    for (int i = blockIdx.x * 256 + threadIdx.x; i < n; i += 256 * 256)
        out_ops[i] *= inv;
}

// ---------------- launch ----------------
extern "C" void kernel_launch(void* const* d_in, const int* in_sizes, int n_in,
                              void* d_out, int out_size)
{
    int ix = -1;
    for (int i = 0; i < n_in; i++) {
        if (in_sizes[i] == MAXN * E) { ix = i; break; }
    }
    if (ix < 0) return;

    const int*   num_ops = (const int*)d_in[0];
    int D = in_sizes[0];
    const float* x    = (const float*)d_in[ix + 0];
    const float* y    = (const float*)d_in[ix + 1];
    const float* z    = (const float*)d_in[ix + 2];
    const float* omsk = (const float*)d_in[ix + 3];
    const float* pmsk = (const float*)d_in[ix + 4];
    const float* opW1 = (const float*)d_in[ix + 5];
    const float* opb1 = (const float*)d_in[ix + 6];
    const float* opW2 = (const float*)d_in[ix + 7];
    const float* opb2 = (const float*)d_in[ix + 8];
    const float* opW3 = (const float*)d_in[ix + 9];
    const float* opb3 = (const float*)d_in[ix + 10];
    const float* prW1 = (const float*)d_in[ix + 11];
    const float* prb1 = (const float*)d_in[ix + 12];
    const float* prW2 = (const float*)d_in[ix + 13];
    const float* prb2 = (const float*)d_in[ix + 14];
    const float* prW3 = (const float*)d_in[ix + 15];
    const float* prb3 = (const float*)d_in[ix + 16];

    int n = in_sizes[ix] / E;
    int W = in_sizes[ix + 4] / D;
    float* out_ops = (float*)d_out;
    float* out_pr  = out_ops + n;
    (void)out_size;

    cudaFuncSetAttribute(k_op,  cudaFuncAttributeMaxDynamicSharedMemorySize, OP_SMEM_TOTAL);
    cudaFuncSetAttribute(k_pre, cudaFuncAttributeMaxDynamicSharedMemorySize, PRE_SMEM);

    k_scan<<<1, 1024>>>(num_ops, D, z, opW1, opb1, prW1, prb1);
    k_pre<<<2 * (D / 16), 256, PRE_SMEM>>>(y, opW1, prW1, D);
    k_op<<<(n + 63) / 64, 256, OP_SMEM_TOTAL>>>(x, opW1, opW2, opb2, opW3, opb3, omsk, n);
    k_exp_prlvl<<<256 + D / 4, 256>>>(out_ops, n, prW1, prW2, prb2, prW3, prb3, pmsk, out_pr, W);
    k_norm<<<256, 256>>>(out_ops, n);
}

// round 5
// speedup vs baseline: 1.9197x; 1.3111x over previous
#include <cuda_runtime.h>
#include <cuda_bf16.h>
#include <math.h>

#define E      256
#define H1     32
#define H2     16
#define MAXD   1024
#define MAXN   (1024*100)

typedef unsigned long long ull;

// ---------------- device scratch ----------------
__device__ int      g_dagids[MAXN];
__device__ int      g_offsets[MAXD + 1];
__device__ float    g_yop[MAXD * H1];
__device__ float    g_ypr[MAXD * H1];
__device__ float    g_czop[H1];
__device__ float    g_czpr[H1];
__device__ float    g_partials[2048];
__device__ ull      g_wpk[4096];       // opW1 x-part repacked [k4][lane][2] pairs

__device__ __forceinline__ ull ffma2(ull a, ull b, ull c) {
    ull d;
    asm("fma.rn.f32x2 %0, %1, %2, %3;" : "=l"(d) : "l"(a), "l"(b), "l"(c));
    return d;
}
__device__ __forceinline__ ull pack2(float lo, float hi) {
    return (ull)__float_as_uint(lo) | ((ull)__float_as_uint(hi) << 32);
}
__device__ __forceinline__ float unpack_sum(ull v) {
    return __uint_as_float((unsigned)(v & 0xffffffffu)) +
           __uint_as_float((unsigned)(v >> 32));
}

// ---------------- K0: scan num_ops -> offsets; z-part constants ----------------
__global__ void k_scan(const int* __restrict__ num_ops, int D,
                       const float* __restrict__ z,
                       const float* __restrict__ opW1, const float* __restrict__ opb1,
                       const float* __restrict__ prW1, const float* __restrict__ prb1)
{
    __shared__ int   s[1024];
    __shared__ float sred[1024];
    int t = threadIdx.x;
    s[t] = (t < D) ? num_ops[t] : 0;
    __syncthreads();
    #pragma unroll
    for (int off = 1; off < 1024; off <<= 1) {
        int v = (t >= off) ? s[t - off] : 0;
        __syncthreads();
        s[t] += v;
        __syncthreads();
    }
    if (t == 0) g_offsets[0] = 0;
    if (t < D) g_offsets[t + 1] = s[t];

    {
        int j = t & 31;
        int c = (t >> 5) & 15;
        float a = 0.f;
        if (t < 512) {
            #pragma unroll
            for (int kk = 0; kk < 16; kk++) {
                int k = c * 16 + kk;
                a += z[k] * opW1[(2 * E + k) * H1 + j];
            }
        } else {
            #pragma unroll
            for (int kk = 0; kk < 16; kk++) {
                int k = c * 16 + kk;
                a += z[k] * prW1[(1 + E + k) * H1 + j];
            }
        }
        sred[t] = a;
    }
    __syncthreads();
    if (t < 32) {
        float a = opb1[t];
        #pragma unroll
        for (int c = 0; c < 16; c++) a += sred[t + 32 * c];
        g_czop[t] = a;
    } else if (t >= 512 && t < 544) {
        int j = t - 512;
        float a = prb1[j];
        #pragma unroll
        for (int c = 0; c < 16; c++) a += sred[512 + j + 32 * c];
        g_czpr[j] = a;
    }
}

// ---------------- K1: y@W1y precompute + dagfill + W1-repack ----------------
#define PRE_SMEM (32768 + 32768 + 16384)
__global__ void __launch_bounds__(256)
k_pre(const float* __restrict__ y,
      const float* __restrict__ opW1,
      const float* __restrict__ prW1, int D)
{
    extern __shared__ unsigned char sm_raw[];
    int nb = D / 16;
    if (blockIdx.x == 2 * nb) {
        // repack opW1 x-part: g_wpk[2*(k4*32+j)+c] = (W[4k4+2c][j], W[4k4+2c+1][j])
        for (int idx = threadIdx.x; idx < 4096; idx += 256) {
            int p = idx >> 1, c = idx & 1;
            int k4 = p >> 5, j = p & 31;
            g_wpk[idx] = pack2(opW1[(4 * k4 + 2 * c) * H1 + j],
                               opW1[(4 * k4 + 2 * c + 1) * H1 + j]);
        }
        return;
    }
    if (blockIdx.x >= nb) {
        int d0 = (blockIdx.x - nb) * 16;
        for (int d = d0; d < d0 + 16; d++) {
            int s = g_offsets[d], e = g_offsets[d + 1];
            for (int i = s + threadIdx.x; i < e; i += 256) g_dagids[i] = d;
        }
        return;
    }
    ull* swop = (ull*)sm_raw;
    ull* swpr = (ull*)(sm_raw + 32768);
    ull* syu  = (ull*)(sm_raw + 65536);

    int tid = threadIdx.x;
    int d0 = blockIdx.x * 16;

    for (int idx = tid; idx < 128 * 32; idx += 256) {
        int k2 = idx >> 5, j = idx & 31;
        swop[idx] = pack2(opW1[(E + 2 * k2) * H1 + j],
                          opW1[(E + 2 * k2 + 1) * H1 + j]);
        swpr[idx] = pack2(prW1[(1 + 2 * k2) * H1 + j],
                          prW1[(1 + 2 * k2 + 1) * H1 + j]);
    }
    {
        const float4* ysrc = (const float4*)(y + (size_t)d0 * E);
        float4* ydst = (float4*)syu;
        for (int idx = tid; idx < 16 * E / 4; idx += 256) ydst[idx] = ysrc[idx];
    }
    __syncthreads();

    int warp = tid >> 5, lane = tid & 31;
    for (int slot = warp; slot < 32; slot += 8) {
        int dag = slot & 15, br = slot >> 4;
        const ull* w = br ? swpr : swop;
        const ull* xr = syu + dag * 128;
        ull acc = 0;
        #pragma unroll 16
        for (int k2 = 0; k2 < 128; k2++)
            acc = ffma2(xr[k2], w[k2 * 32 + lane], acc);
        float v = unpack_sum(acc);
        if (br) g_ypr[(d0 + dag) * H1 + lane] = v;
        else    g_yop[(d0 + dag) * H1 + lane] = v;
    }
}

// ---------------- K2: main op MLP + exp + partials ; prlvl blocks appended ----------------
#define OP_SMEM_SXU   0                       // 64*128 ull = 65536
#define OP_SMEM_SWP   65536                   // 4096 ull = 32768
#define OP_SMEM_SW2   98304                   // 512 f
#define OP_SMEM_SW3   100352
#define OP_SMEM_SB2   100416
#define OP_SMEM_SH    100480                  // 8*8*33 f = 8448
#define OP_SMEM_SRED  108928                  // 8 f
#define OP_SMEM_TOTAL 109056
__global__ void __launch_bounds__(256, 2)
k_op(const float* __restrict__ x,
     const float* __restrict__ opW2, const float* __restrict__ opb2,
     const float* __restrict__ opW3, const float* __restrict__ opb3,
     const float* __restrict__ omsk, int n, int nb_op,
     const float* __restrict__ prW1, const float* __restrict__ prW2,
     const float* __restrict__ prb2, const float* __restrict__ prW3,
     const float* __restrict__ prb3, const float* __restrict__ pmsk,
     float* __restrict__ out_ops, float* __restrict__ out_pr, int W)
{
    extern __shared__ unsigned char sm_raw[];
    int tid = threadIdx.x;

    if (blockIdx.x >= nb_op) {
        // ---------- prlvl: 4 dags per block, W=64 workers ----------
        float* sm   = (float*)sm_raw;
        float* sYP  = sm;          // [4][32]
        float* sr0  = sm + 128;    // [32]
        float* sW2p = sm + 160;    // [512]
        float* sW3p = sm + 672;    // [16]
        float* sb2p = sm + 688;    // [16]
        float* red  = sm + 704;    // [4][64]
        int pb = blockIdx.x - nb_op;
        int d0 = pb * 4, g = tid >> 6, wk = tid & 63;
        int dag = d0 + g;

        if (tid < 128) {
            int gg = tid >> 5, j = tid & 31;
            sYP[gg * 32 + j] = g_ypr[(d0 + gg) * H1 + j] + g_czpr[j];
        }
        if (tid < H1) sr0[tid] = prW1[tid];
        for (int i = tid; i < H1 * H2; i += 256) sW2p[i] = prW2[i];
        if (tid < H2) { sW3p[tid] = prW3[tid]; sb2p[tid] = prb2[tid]; }
        __syncthreads();

        float lim = (float)(wk + 1);
        float h2[H2];
        #pragma unroll
        for (int m = 0; m < H2; m++) h2[m] = sb2p[m];
        #pragma unroll 4
        for (int j = 0; j < H1; j++) {
            float h1 = fmaxf(sYP[g * 32 + j] + lim * sr0[j], 0.f);
            #pragma unroll
            for (int m = 0; m < H2; m++) h2[m] += h1 * sW2p[j * H2 + m];
        }
        float lg = prb3[0];
        #pragma unroll
        for (int m = 0; m < H2; m++) lg += fmaxf(h2[m], 0.f) * sW3p[m];
        lg -= (1.f - pmsk[(size_t)dag * W + wk]) * 1000.f;

        red[g * 64 + wk] = lg;
        __syncthreads();
        for (int st = 32; st > 0; st >>= 1) {
            if (wk < st) red[g * 64 + wk] = fmaxf(red[g * 64 + wk], red[g * 64 + wk + st]);
            __syncthreads();
        }
        float mx = red[g * 64];
        __syncthreads();
        float ev = expf(lg - mx);
        red[g * 64 + wk] = ev;
        __syncthreads();
        for (int st = 32; st > 0; st >>= 1) {
            if (wk < st) red[g * 64 + wk] += red[g * 64 + wk + st];
            __syncthreads();
        }
        out_pr[(size_t)dag * W + wk] = ev / red[g * 64];
        return;
    }

    // ---------- op branch ----------
    ull*   sxu  = (ull*)(sm_raw + OP_SMEM_SXU);
    ull*   swp  = (ull*)(sm_raw + OP_SMEM_SWP);
    float* sW2  = (float*)(sm_raw + OP_SMEM_SW2);
    float* sW3  = (float*)(sm_raw + OP_SMEM_SW3);
    float* sb2  = (float*)(sm_raw + OP_SMEM_SB2);
    float* sH   = (float*)(sm_raw + OP_SMEM_SH);
    float* sRed = (float*)(sm_raw + OP_SMEM_SRED);

    int base = blockIdx.x * 64;

    // stage x tile (coalesced float4)
    {
        const float4* src = (const float4*)(x + (size_t)base * E);
        float4* dst = (float4*)sxu;
        if (base + 64 <= n) {
            #pragma unroll 4
            for (int idx = tid; idx < 4096; idx += 256) dst[idx] = src[idx];
        } else {
            for (int idx = tid; idx < 4096; idx += 256) {
                int row = idx >> 6;
                int gi = min(base + row, n - 1);
                dst[idx] = ((const float4*)(x + (size_t)gi * E))[idx & 63];
            }
        }
    }
    // stage packed W1 (coalesced float4 from repacked buffer)
    {
        const float4* ws = (const float4*)g_wpk;
        float4* wd = (float4*)swp;
        #pragma unroll 4
        for (int idx = tid; idx < 2048; idx += 256) wd[idx] = ws[idx];
    }
    for (int i = tid; i < H1 * H2; i += 256) sW2[i] = opW2[i];
    if (tid < H2) { sW3[tid] = opW3[tid]; sb2[tid] = opb2[tid]; }
    __syncthreads();

    int warp = tid >> 5, lane = tid & 31;

    ull acc[8];
    {
        float cz = g_czop[lane];
        #pragma unroll
        for (int u = 0; u < 8; u++) {
            int i = min(base + warp * 8 + u, n - 1);
            acc[u] = pack2(g_yop[g_dagids[i] * H1 + lane] + cz, 0.f);
        }
    }

    const ulonglong2* wq = (const ulonglong2*)swp;
    const ulonglong2* xq = (const ulonglong2*)(sxu + warp * 8 * 128);
    #pragma unroll 4
    for (int k4 = 0; k4 < 64; k4++) {
        ulonglong2 w = wq[k4 * 32 + lane];
        #pragma unroll
        for (int u = 0; u < 8; u++) {
            ulonglong2 xv = xq[u * 64 + k4];
            acc[u] = ffma2(xv.x, w.x, acc[u]);
            acc[u] = ffma2(xv.y, w.y, acc[u]);
        }
    }

    float* sHw = sH + warp * (8 * 33);
    #pragma unroll
    for (int u = 0; u < 8; u++)
        sHw[u * 33 + lane] = fmaxf(unpack_sum(acc[u]), 0.f);
    __syncwarp();

    // layers 2+3: lane -> (op o = lane>>2, group m = lane&3)
    int o = lane >> 2, m = lane & 3;
    float h2[4];
    #pragma unroll
    for (int q = 0; q < 4; q++) h2[q] = sb2[m + 4 * q];
    const float* hrow = sHw + o * 33;
    #pragma unroll
    for (int j = 0; j < H1; j++) {
        float h = hrow[j];
        #pragma unroll
        for (int q = 0; q < 4; q++) h2[q] += h * sW2[j * H2 + m + 4 * q];
    }
    float part = 0.f;
    #pragma unroll
    for (int q = 0; q < 4; q++) part += fmaxf(h2[q], 0.f) * sW3[m + 4 * q];
    part += __shfl_xor_sync(0xffffffffu, part, 1);
    part += __shfl_xor_sync(0xffffffffu, part, 2);

    float e = 0.f;
    {
        int i = base + warp * 8 + o;
        if (m == 0 && i < n) {
            float lg = part + opb3[0] - (1.f - omsk[i]) * 1000.f;
            e = expf(lg);
            out_ops[i] = e;
        }
    }
    // deterministic warp sum (non-writers hold 0)
    e += __shfl_xor_sync(0xffffffffu, e, 1);
    e += __shfl_xor_sync(0xffffffffu, e, 2);
    e += __shfl_xor_sync(0xffffffffu, e, 4);
    e += __shfl_xor_sync(0xffffffffu, e, 8);
    e += __shfl_xor_sync(0xffffffffu, e, 16);
    if (lane == 0) sRed[warp] = e;
    __syncthreads();
    if (tid == 0) {
        float s = 0.f;
        #pragma unroll
        for (int w = 0; w < 8; w++) s += sRed[w];
        g_partials[blockIdx.x] = s;
    }
}

// ---------------- K3: deterministic reduce of partials + normalize ----------------
__global__ void __launch_bounds__(256)
k_norm(float* __restrict__ out_ops, int n, int nb_op)
{
    __shared__ float red[256];
    int t = threadIdx.x;
    float s = 0.f;
    for (int q = t; q < nb_op; q += 256) s += g_partials[q];
    red[t] = s;
    __syncthreads();
    for (int st = 128; st > 0; st >>= 1) {
        if (t < st) red[t] += red[t + st];
        __syncthreads();
    }
    float inv = 1.f / red[0];
    for (int i = blockIdx.x * 256 + t; i < n; i += 256 * 256)
        out_ops[i] *= inv;
}

// ---------------- launch ----------------
extern "C" void kernel_launch(void* const* d_in, const int* in_sizes, int n_in,
                              void* d_out, int out_size)
{
    int ix = -1;
    for (int i = 0; i < n_in; i++) {
        if (in_sizes[i] == MAXN * E) { ix = i; break; }
    }
    if (ix < 0) return;

    const int*   num_ops = (const int*)d_in[0];
    int D = in_sizes[0];
    const float* x    = (const float*)d_in[ix + 0];
    const float* y    = (const float*)d_in[ix + 1];
    const float* z    = (const float*)d_in[ix + 2];
    const float* omsk = (const float*)d_in[ix + 3];
    const float* pmsk = (const float*)d_in[ix + 4];
    const float* opW1 = (const float*)d_in[ix + 5];
    const float* opb1 = (const float*)d_in[ix + 6];
    const float* opW2 = (const float*)d_in[ix + 7];
    const float* opb2 = (const float*)d_in[ix + 8];
    const float* opW3 = (const float*)d_in[ix + 9];
    const float* opb3 = (const float*)d_in[ix + 10];
    const float* prW1 = (const float*)d_in[ix + 11];
    const float* prb1 = (const float*)d_in[ix + 12];
    const float* prW2 = (const float*)d_in[ix + 13];
    const float* prb2 = (const float*)d_in[ix + 14];
    const float* prW3 = (const float*)d_in[ix + 15];
    const float* prb3 = (const float*)d_in[ix + 16];

    int n = in_sizes[ix] / E;
    int W = in_sizes[ix + 4] / D;
    int nb_op = (n + 63) / 64;
    float* out_ops = (float*)d_out;
    float* out_pr  = out_ops + n;
    (void)out_size;

    cudaFuncSetAttribute(k_op,  cudaFuncAttributeMaxDynamicSharedMemorySize, OP_SMEM_TOTAL);
    cudaFuncSetAttribute(k_pre, cudaFuncAttributeMaxDynamicSharedMemorySize, PRE_SMEM);

    k_scan<<<1, 1024>>>(num_ops, D, z, opW1, opb1, prW1, prb1);
    k_pre<<<2 * (D / 16) + 1, 256, PRE_SMEM>>>(y, opW1, prW1, D);
    k_op<<<nb_op + D / 4, 256, OP_SMEM_TOTAL>>>(x, opW2, opb2, opW3, opb3, omsk, n, nb_op,
                                                prW1, prW2, prb2, prW3, prb3, pmsk,
                                                out_ops, out_pr, W);
    k_norm<<<256, 256>>>(out_ops, n, nb_op);
}

// round 6
// speedup vs baseline: 2.1088x; 1.0985x over previous
#include <cuda_runtime.h>
#include <cuda_bf16.h>
#include <math.h>

#define E      256
#define H1     32
#define H2     16
#define MAXD   1024
#define MAXN   (1024*100)

typedef unsigned long long ull;

// ---------------- device scratch ----------------
__device__ int      g_dagids[MAXN];
__device__ float    g_yop[MAXD * H1];
__device__ float    g_ypr[MAXD * H1];
__device__ float    g_czop[H1];
__device__ float    g_czpr[H1];
__device__ float    g_partials[2048];
__device__ ull      g_wpk[4096];       // opW1 x-part repacked: ull2[k4][lane]

__device__ __forceinline__ ull ffma2(ull a, ull b, ull c) {
    ull d;
    asm("fma.rn.f32x2 %0, %1, %2, %3;" : "=l"(d) : "l"(a), "l"(b), "l"(c));
    return d;
}
__device__ __forceinline__ ull pack2(float lo, float hi) {
    return (ull)__float_as_uint(lo) | ((ull)__float_as_uint(hi) << 32);
}
__device__ __forceinline__ float unpack_sum(ull v) {
    return __uint_as_float((unsigned)(v & 0xffffffffu)) +
           __uint_as_float((unsigned)(v >> 32));
}

// ---------------- K1: y@W1y precompute + dagfill(local scan) + repack + cz ----------------
#define PRE_SMEM (32768 + 32768 + 16384)
__global__ void __launch_bounds__(256)
k_pre(const float* __restrict__ y,
      const float* __restrict__ opW1, const float* __restrict__ opb1,
      const float* __restrict__ prW1, const float* __restrict__ prb1,
      const float* __restrict__ z,
      const int* __restrict__ num_ops, int D)
{
    extern __shared__ unsigned char sm_raw[];
    int nb = D / 16;
    int tid = threadIdx.x;

    if (blockIdx.x == 2 * nb) {
        // repack opW1 x-part: pairs (W[4k4+2c][j], W[4k4+2c+1][j])
        for (int idx = tid; idx < 4096; idx += 256) {
            int p = idx >> 1, c = idx & 1;
            int k4 = p >> 5, j = p & 31;
            g_wpk[idx] = pack2(opW1[(4 * k4 + 2 * c) * H1 + j],
                               opW1[(4 * k4 + 2 * c + 1) * H1 + j]);
        }
        return;
    }
    if (blockIdx.x == 2 * nb + 1) {
        // cz for both branches: 2 branches x 32 j x 4 chunks of 64 k
        __shared__ float sred[256];
        int j = tid & 31, c = (tid >> 5) & 3, br = tid >> 7;
        float a = 0.f;
        if (br == 0) {
            #pragma unroll 8
            for (int kk = 0; kk < 64; kk++) {
                int k = c * 64 + kk;
                a += z[k] * opW1[(2 * E + k) * H1 + j];
            }
        } else {
            #pragma unroll 8
            for (int kk = 0; kk < 64; kk++) {
                int k = c * 64 + kk;
                a += z[k] * prW1[(1 + E + k) * H1 + j];
            }
        }
        sred[tid] = a;
        __syncthreads();
        if (tid < 32)
            g_czop[tid] = opb1[tid] + sred[tid] + sred[tid + 32] + sred[tid + 64] + sred[tid + 96];
        else if (tid >= 128 && tid < 160) {
            int jj = tid - 128;
            g_czpr[jj] = prb1[jj] + sred[128 + jj] + sred[160 + jj] + sred[192 + jj] + sred[224 + jj];
        }
        return;
    }
    if (blockIdx.x >= nb) {
        // dagfill with block-local scan of num_ops
        __shared__ int sc[256];
        __shared__ int sstart[17];
        int b = blockIdx.x - nb, d0 = b * 16;
        int a = 0;
        #pragma unroll
        for (int q = 0; q < 4; q++) {
            int idx = tid * 4 + q;
            a += (idx < D) ? num_ops[idx] : 0;
        }
        sc[tid] = a;
        __syncthreads();
        #pragma unroll
        for (int off = 1; off < 256; off <<= 1) {
            int v = (tid >= off) ? sc[tid - off] : 0;
            __syncthreads();
            sc[tid] += v;
            __syncthreads();
        }
        if (tid <= 16) {
            int d = d0 + tid;
            int s = (d >> 2) ? sc[(d >> 2) - 1] : 0;
            for (int q = d & ~3; q < d; q++) s += num_ops[q];
            sstart[tid] = s;
        }
        __syncthreads();
        for (int dd = 0; dd < 16; dd++) {
            int s = sstart[dd], e = sstart[dd + 1];
            for (int i = s + tid; i < e; i += 256) g_dagids[i] = d0 + dd;
        }
        return;
    }

    // ---- y-precompute: 16 dags per block, both branches ----
    ull* swop = (ull*)sm_raw;
    ull* swpr = (ull*)(sm_raw + 32768);
    ull* syu  = (ull*)(sm_raw + 65536);
    int d0 = blockIdx.x * 16;

    for (int idx = tid; idx < 128 * 32; idx += 256) {
        int k2 = idx >> 5, j = idx & 31;
        swop[idx] = pack2(opW1[(E + 2 * k2) * H1 + j],
                          opW1[(E + 2 * k2 + 1) * H1 + j]);
        swpr[idx] = pack2(prW1[(1 + 2 * k2) * H1 + j],
                          prW1[(1 + 2 * k2 + 1) * H1 + j]);
    }
    {
        const float4* ysrc = (const float4*)(y + (size_t)d0 * E);
        float4* ydst = (float4*)syu;
        for (int idx = tid; idx < 16 * E / 4; idx += 256) ydst[idx] = ysrc[idx];
    }
    __syncthreads();

    int warp = tid >> 5, lane = tid & 31;
    for (int slot = warp; slot < 32; slot += 8) {
        int dag = slot & 15, br = slot >> 4;
        const ull* w = br ? swpr : swop;
        const ull* xr = syu + dag * 128;
        ull acc = 0;
        #pragma unroll 16
        for (int k2 = 0; k2 < 128; k2++)
            acc = ffma2(xr[k2], w[k2 * 32 + lane], acc);
        float v = unpack_sum(acc);
        if (br) g_ypr[(d0 + dag) * H1 + lane] = v;
        else    g_yop[(d0 + dag) * H1 + lane] = v;
    }
}

// ---------------- K2: main op MLP (128 ops/block, u=16, split-K) + prlvl ----------------
#define OP_SMEM_SXU   0                       // 128 ops * 32 f4 = 4096 f4 = 65536 B (per stage)
#define OP_SMEM_SWP   65536                   // 4096 ull = 32768
#define OP_SMEM_SW2   98304                   // 512 f = 2048
#define OP_SMEM_SW3   100352                  // 16 f
#define OP_SMEM_SB2   100416                  // 16 f
#define OP_SMEM_SRED  100480                  // 8 f
#define OP_SMEM_TOTAL 100544
__global__ void __launch_bounds__(256, 2)
k_op(const float* __restrict__ x,
     const float* __restrict__ opW2, const float* __restrict__ opb2,
     const float* __restrict__ opW3, const float* __restrict__ opb3,
     const float* __restrict__ omsk, int n, int nb_op,
     const float* __restrict__ prW1, const float* __restrict__ prW2,
     const float* __restrict__ prb2, const float* __restrict__ prW3,
     const float* __restrict__ prb3, const float* __restrict__ pmsk,
     float* __restrict__ out_ops, float* __restrict__ out_pr, int W)
{
    extern __shared__ unsigned char sm_raw[];
    int tid = threadIdx.x;

    if (blockIdx.x >= nb_op) {
        // ---------- prlvl: 4 dags per block, W=64 workers ----------
        float* sm   = (float*)sm_raw;
        float* sYP  = sm;          // [4][32]
        float* sr0  = sm + 128;    // [32]
        float* sW2p = sm + 160;    // [512]
        float* sW3p = sm + 672;    // [16]
        float* sb2p = sm + 688;    // [16]
        float* red  = sm + 704;    // [4][64]
        int pb = blockIdx.x - nb_op;
        int d0 = pb * 4, g = tid >> 6, wk = tid & 63;
        int dag = d0 + g;

        if (tid < 128) {
            int gg = tid >> 5, j = tid & 31;
            sYP[gg * 32 + j] = g_ypr[(d0 + gg) * H1 + j] + g_czpr[j];
        }
        if (tid < H1) sr0[tid] = prW1[tid];
        for (int i = tid; i < H1 * H2; i += 256) sW2p[i] = prW2[i];
        if (tid < H2) { sW3p[tid] = prW3[tid]; sb2p[tid] = prb2[tid]; }
        __syncthreads();

        float lim = (float)(wk + 1);
        float h2[H2];
        #pragma unroll
        for (int m = 0; m < H2; m++) h2[m] = sb2p[m];
        #pragma unroll 4
        for (int j = 0; j < H1; j++) {
            float h1 = fmaxf(sYP[g * 32 + j] + lim * sr0[j], 0.f);
            #pragma unroll
            for (int m = 0; m < H2; m++) h2[m] += h1 * sW2p[j * H2 + m];
        }
        float lg = prb3[0];
        #pragma unroll
        for (int m = 0; m < H2; m++) lg += fmaxf(h2[m], 0.f) * sW3p[m];
        lg -= (1.f - pmsk[(size_t)dag * W + wk]) * 1000.f;

        red[g * 64 + wk] = lg;
        __syncthreads();
        for (int st = 32; st > 0; st >>= 1) {
            if (wk < st) red[g * 64 + wk] = fmaxf(red[g * 64 + wk], red[g * 64 + wk + st]);
            __syncthreads();
        }
        float mx = red[g * 64];
        __syncthreads();
        float ev = expf(lg - mx);
        red[g * 64 + wk] = ev;
        __syncthreads();
        for (int st = 32; st > 0; st >>= 1) {
            if (wk < st) red[g * 64 + wk] += red[g * 64 + wk + st];
            __syncthreads();
        }
        out_pr[(size_t)dag * W + wk] = ev / red[g * 64];
        return;
    }

    // ---------- op branch: 128 ops/block ----------
    float4* sxu  = (float4*)(sm_raw + OP_SMEM_SXU);
    ull*    swp  = (ull*)(sm_raw + OP_SMEM_SWP);
    float*  sW2  = (float*)(sm_raw + OP_SMEM_SW2);
    float*  sW3  = (float*)(sm_raw + OP_SMEM_SW3);
    float*  sb2  = (float*)(sm_raw + OP_SMEM_SB2);
    float*  sRed = (float*)(sm_raw + OP_SMEM_SRED);

    int base = blockIdx.x * 128;
    int warp = tid >> 5, lane = tid & 31;

    // stage packed W1 (full 32 KB, both K halves)
    {
        const float4* ws = (const float4*)g_wpk;
        float4* wd = (float4*)swp;
        #pragma unroll 4
        for (int idx = tid; idx < 2048; idx += 256) wd[idx] = ws[idx];
    }
    for (int i = tid; i < H1 * H2; i += 256) sW2[i] = opW2[i];
    if (tid < H2) { sW3[tid] = opW3[tid]; sb2[tid] = opb2[tid]; }

    // init accumulators (lo = y-part + z-part, hi = 0)
    ull acc[16];
    {
        float cz = g_czop[lane];
        #pragma unroll
        for (int u = 0; u < 16; u++) {
            int i = min(base + warp * 16 + u, n - 1);
            acc[u] = pack2(g_yop[g_dagids[i] * H1 + lane] + cz, 0.f);
        }
    }

    const ulonglong2* wq = (const ulonglong2*)swp;
    bool full = (base + 128 <= n);

    #pragma unroll
    for (int s = 0; s < 2; s++) {
        // stage x half-tile: 128 ops x 32 float4
        if (full) {
            #pragma unroll 4
            for (int idx = tid; idx < 4096; idx += 256) {
                int op = idx >> 5, col = idx & 31;
                sxu[idx] = ((const float4*)x)[(size_t)(base + op) * 64 + s * 32 + col];
            }
        } else {
            for (int idx = tid; idx < 4096; idx += 256) {
                int op = idx >> 5, col = idx & 31;
                int gi = min(base + op, n - 1);
                sxu[idx] = ((const float4*)x)[(size_t)gi * 64 + s * 32 + col];
            }
        }
        __syncthreads();

        const ulonglong2* xq = (const ulonglong2*)sxu + (warp * 16) * 32;
        #pragma unroll 4
        for (int k4 = 0; k4 < 32; k4++) {
            ulonglong2 w = wq[(s * 32 + k4) * 32 + lane];
            #pragma unroll
            for (int u = 0; u < 16; u++) {
                ulonglong2 xv = xq[u * 32 + k4];
                acc[u] = ffma2(xv.x, w.x, acc[u]);
                acc[u] = ffma2(xv.y, w.y, acc[u]);
            }
        }
        __syncthreads();
    }

    // h1 transpose into this warp's (dead) x region: 16*33 floats
    float* sHw = (float*)((unsigned char*)sxu + warp * 8192);
    #pragma unroll
    for (int u = 0; u < 16; u++)
        sHw[u * 33 + lane] = fmaxf(unpack_sum(acc[u]), 0.f);
    __syncwarp();

    // layers 2+3: lane -> (op o2 = lane>>1, neuron half m2 = lane&1)
    int o2 = lane >> 1, m2 = lane & 1;
    float h2[8];
    #pragma unroll
    for (int q = 0; q < 8; q++) h2[q] = sb2[m2 * 8 + q];
    const float* hrow = sHw + o2 * 33;
    #pragma unroll 8
    for (int j = 0; j < H1; j++) {
        float h = hrow[j];
        #pragma unroll
        for (int q = 0; q < 8; q++) h2[q] += h * sW2[j * H2 + m2 * 8 + q];
    }
    float part = 0.f;
    #pragma unroll
    for (int q = 0; q < 8; q++) part += fmaxf(h2[q], 0.f) * sW3[m2 * 8 + q];
    part += __shfl_xor_sync(0xffffffffu, part, 1);

    float e = 0.f;
    {
        int i = base + warp * 16 + o2;
        if (m2 == 0 && i < n) {
            float lg = part + opb3[0] - (1.f - omsk[i]) * 1000.f;
            e = expf(lg);
            out_ops[i] = e;
        }
    }
    // deterministic warp sum (non-writers hold 0)
    e += __shfl_xor_sync(0xffffffffu, e, 1);
    e += __shfl_xor_sync(0xffffffffu, e, 2);
    e += __shfl_xor_sync(0xffffffffu, e, 4);
    e += __shfl_xor_sync(0xffffffffu, e, 8);
    e += __shfl_xor_sync(0xffffffffu, e, 16);
    if (lane == 0) sRed[warp] = e;
    __syncthreads();
    if (tid == 0) {
        float sum = 0.f;
        #pragma unroll
        for (int w = 0; w < 8; w++) sum += sRed[w];
        g_partials[blockIdx.x] = sum;
    }
}

// ---------------- K3: deterministic reduce of partials + normalize ----------------
__global__ void __launch_bounds__(256)
k_norm(float* __restrict__ out_ops, int n, int nb_op)
{
    __shared__ float red[256];
    int t = threadIdx.x;
    float s = 0.f;
    for (int q = t; q < nb_op; q += 256) s += g_partials[q];
    red[t] = s;
    __syncthreads();
    for (int st = 128; st > 0; st >>= 1) {
        if (t < st) red[t] += red[t + st];
        __syncthreads();
    }
    float inv = 1.f / red[0];
    for (int i = blockIdx.x * 256 + t; i < n; i += 256 * 256)
        out_ops[i] *= inv;
}

// ---------------- launch ----------------
extern "C" void kernel_launch(void* const* d_in, const int* in_sizes, int n_in,
                              void* d_out, int out_size)
{
    int ix = -1;
    for (int i = 0; i < n_in; i++) {
        if (in_sizes[i] == MAXN * E) { ix = i; break; }
    }
    if (ix < 0) return;

    const int*   num_ops = (const int*)d_in[0];
    int D = in_sizes[0];
    const float* x    = (const float*)d_in[ix + 0];
    const float* y    = (const float*)d_in[ix + 1];
    const float* z    = (const float*)d_in[ix + 2];
    const float* omsk = (const float*)d_in[ix + 3];
    const float* pmsk = (const float*)d_in[ix + 4];
    const float* opW1 = (const float*)d_in[ix + 5];
    const float* opb1 = (const float*)d_in[ix + 6];
    const float* opW2 = (const float*)d_in[ix + 7];
    const float* opb2 = (const float*)d_in[ix + 8];
    const float* opW3 = (const float*)d_in[ix + 9];
    const float* opb3 = (const float*)d_in[ix + 10];
    const float* prW1 = (const float*)d_in[ix + 11];
    const float* prb1 = (const float*)d_in[ix + 12];
    const float* prW2 = (const float*)d_in[ix + 13];
    const float* prb2 = (const float*)d_in[ix + 14];
    const float* prW3 = (const float*)d_in[ix + 15];
    const float* prb3 = (const float*)d_in[ix + 16];

    int n = in_sizes[ix] / E;
    int W = in_sizes[ix + 4] / D;
    int nb_op = (n + 127) / 128;
    float* out_ops = (float*)d_out;
    float* out_pr  = out_ops + n;
    (void)out_size;

    cudaFuncSetAttribute(k_op,  cudaFuncAttributeMaxDynamicSharedMemorySize, OP_SMEM_TOTAL);
    cudaFuncSetAttribute(k_pre, cudaFuncAttributeMaxDynamicSharedMemorySize, PRE_SMEM);

    k_pre<<<2 * (D / 16) + 2, 256, PRE_SMEM>>>(y, opW1, opb1, prW1, prb1, z, num_ops, D);
    k_op<<<nb_op + D / 4, 256, OP_SMEM_TOTAL>>>(x, opW2, opb2, opW3, opb3, omsk, n, nb_op,
                                                prW1, prW2, prb2, prW3, prb3, pmsk,
                                                out_ops, out_pr, W);
    k_norm<<<256, 256>>>(out_ops, n, nb_op);
}

// round 8
// speedup vs baseline: 2.4500x; 1.1618x over previous
#include <cuda_runtime.h>
#include <cuda_bf16.h>
#include <math.h>

#define E      256
#define H1     32
#define H2     16
#define MAXD   1024
#define MAXN   (1024*100)

typedef unsigned long long ull;

// ---------------- device scratch ----------------
__device__ int      g_dagids[MAXN];
__device__ float    g_yop[MAXD * H1];
__device__ float    g_ypr[MAXD * H1];
__device__ float    g_czop[H1];
__device__ float    g_czpr[H1];
__device__ float    g_partials[2048];
__device__ ull      g_wpk[4096];       // opW1 x-part packed: ull2[k4][lane]

__device__ __forceinline__ ull ffma2(ull a, ull b, ull c) {
    ull d;
    asm("fma.rn.f32x2 %0, %1, %2, %3;" : "=l"(d) : "l"(a), "l"(b), "l"(c));
    return d;
}
__device__ __forceinline__ ull pack2(float lo, float hi) {
    return (ull)__float_as_uint(lo) | ((ull)__float_as_uint(hi) << 32);
}
__device__ __forceinline__ float unpack_sum(ull v) {
    return __uint_as_float((unsigned)(v & 0xffffffffu)) +
           __uint_as_float((unsigned)(v >> 32));
}

// ---------------- K1: y-precompute(8 dags/blk) + dagfill + repack + cz ----------------
#define PRE_SMEM (32768 + 32768 + 8192)
__global__ void __launch_bounds__(256)
k_pre(const float* __restrict__ y,
      const float* __restrict__ opW1, const float* __restrict__ opb1,
      const float* __restrict__ prW1, const float* __restrict__ prb1,
      const float* __restrict__ z,
      const int* __restrict__ num_ops, int D)
{
    extern __shared__ unsigned char sm_raw[];
    int nbY = D / 8;            // 128 y-precompute blocks
    int nbF = D / 16;           // 64 dagfill blocks
    int tid = threadIdx.x;
    int b = blockIdx.x;

    if (b < nbY) {
        // ---- y @ W1y for 8 dags, both branches ----
        float* swop = (float*)sm_raw;                 // [256][32]
        float* swpr = (float*)(sm_raw + 32768);       // [256][32]
        float* sy   = (float*)(sm_raw + 65536);       // [8][256]
        int d0 = b * 8;
        {
            const float4* s1 = (const float4*)(opW1 + E * H1);
            const float4* s2 = (const float4*)(prW1 + H1);
            float4* d1 = (float4*)swop;
            float4* d2 = (float4*)swpr;
            #pragma unroll 4
            for (int i = tid; i < 2048; i += 256) { d1[i] = s1[i]; d2[i] = s2[i]; }
            const float4* ys = (const float4*)(y + (size_t)d0 * E);
            float4* yd = (float4*)sy;
            for (int i = tid; i < 512; i += 256) yd[i] = ys[i];
        }
        __syncthreads();
        int warp = tid >> 5, lane = tid & 31;
        #pragma unroll
        for (int s = 0; s < 2; s++) {
            int slot = warp + 8 * s;       // 16 slots: dag = slot&7, br = slot>>3
            int dag = slot & 7, br = slot >> 3;
            const float* w = br ? swpr : swop;
            const float* yr = sy + dag * 256;
            float a0 = 0.f, a1 = 0.f;
            #pragma unroll 8
            for (int k = 0; k < 256; k += 2) {
                a0 = fmaf(yr[k],     w[k * 32 + lane],       a0);
                a1 = fmaf(yr[k + 1], w[(k + 1) * 32 + lane], a1);
            }
            float v = a0 + a1;
            if (br) g_ypr[(d0 + dag) * H1 + lane] = v;
            else    g_yop[(d0 + dag) * H1 + lane] = v;
        }
        return;
    }
    if (b < nbY + nbF) {
        // ---- dagfill with block-local scan of num_ops ----
        __shared__ int sc[256];
        __shared__ int sstart[17];
        int fb = b - nbY, d0 = fb * 16;
        int a = 0;
        #pragma unroll
        for (int q = 0; q < 4; q++) {
            int idx = tid * 4 + q;
            a += (idx < D) ? num_ops[idx] : 0;
        }
        sc[tid] = a;
        __syncthreads();
        #pragma unroll
        for (int off = 1; off < 256; off <<= 1) {
            int v = (tid >= off) ? sc[tid - off] : 0;
            __syncthreads();
            sc[tid] += v;
            __syncthreads();
        }
        if (tid <= 16) {
            int d = d0 + tid;
            int s = (d >> 2) ? sc[(d >> 2) - 1] : 0;
            for (int q = d & ~3; q < d; q++) s += num_ops[q];
            sstart[tid] = s;
        }
        __syncthreads();
        for (int dd = 0; dd < 16; dd++) {
            int s = sstart[dd], e = sstart[dd + 1];
            for (int i = s + tid; i < e; i += 256) g_dagids[i] = d0 + dd;
        }
        return;
    }
    if (b == nbY + nbF) {
        // ---- repack opW1 x-part into pair layout ----
        for (int idx = tid; idx < 4096; idx += 256) {
            int p = idx >> 1, c = idx & 1;
            int k4 = p >> 5, j = p & 31;
            g_wpk[idx] = pack2(opW1[(4 * k4 + 2 * c) * H1 + j],
                               opW1[(4 * k4 + 2 * c + 1) * H1 + j]);
        }
        return;
    }
    // ---- cz blocks: b == nbY+nbF+1 (op), +2 (pr) ----
    {
        __shared__ float sred[256];
        int br = b - (nbY + nbF + 1);           // 0 = op, 1 = pr
        const float* W  = br ? prW1 : opW1;
        const float* b1 = br ? prb1 : opb1;
        int off = br ? (1 + E) : (2 * E);
        int j = tid & 31, c = tid >> 5;         // 8 chunks x 32 k
        float a0 = 0.f, a1 = 0.f, a2 = 0.f, a3 = 0.f;
        #pragma unroll
        for (int r = 0; r < 8; r++) {
            int k = c * 32 + r * 4;
            a0 = fmaf(z[k],     W[(off + k) * H1 + j],     a0);
            a1 = fmaf(z[k + 1], W[(off + k + 1) * H1 + j], a1);
            a2 = fmaf(z[k + 2], W[(off + k + 2) * H1 + j], a2);
            a3 = fmaf(z[k + 3], W[(off + k + 3) * H1 + j], a3);
        }
        sred[tid] = (a0 + a1) + (a2 + a3);
        __syncthreads();
        if (tid < 32) {
            float s = b1[tid];
            #pragma unroll
            for (int cc = 0; cc < 8; cc++) s += sred[tid + 32 * cc];
            if (br) g_czpr[tid] = s;
            else    g_czop[tid] = s;
        }
    }
}

// ---------------- K2: op MLP (pipelined) + prlvl blocks ----------------
#define OP_SW    0                       // 4096 ull = 32768
#define OP_SX    32768                   // 3 x 1024 float4 = 49152
#define OP_SH    81920                   // 8 warps x 16*33 f = 16896
#define OP_SW2   98816                   // 512 f = 2048
#define OP_SW3   100864                  // 16 f
#define OP_SB2   100928                  // 16 f
#define OP_SRED  100992                  // 8 f
#define OP_TOTAL 101024
__global__ void __launch_bounds__(256, 2)
k_op(const float* __restrict__ x,
     const float* __restrict__ opW2, const float* __restrict__ opb2,
     const float* __restrict__ opW3, const float* __restrict__ opb3,
     const float* __restrict__ omsk, int n, int nb_op,
     const float* __restrict__ prW1, const float* __restrict__ prW2,
     const float* __restrict__ prb2, const float* __restrict__ prW3,
     const float* __restrict__ prb3, const float* __restrict__ pmsk,
     float* __restrict__ out_ops, float* __restrict__ out_pr, int W)
{
    extern __shared__ unsigned char sm_raw[];
    int tid = threadIdx.x;

    if (blockIdx.x >= nb_op) {
        // ---------- prlvl: 4 dags per block, W=64 workers ----------
        float* sm   = (float*)sm_raw;
        float* sYP  = sm;          // [4][32]
        float* sr0  = sm + 128;
        float* sW2p = sm + 160;    // [512]
        float* sW3p = sm + 672;
        float* sb2p = sm + 688;
        float* red  = sm + 704;    // [4][64]
        int pb = blockIdx.x - nb_op;
        int d0 = pb * 4, g = tid >> 6, wk = tid & 63;
        int dag = d0 + g;

        if (tid < 128) {
            int gg = tid >> 5, j = tid & 31;
            sYP[gg * 32 + j] = g_ypr[(d0 + gg) * H1 + j] + g_czpr[j];
        }
        if (tid < H1) sr0[tid] = prW1[tid];
        for (int i = tid; i < H1 * H2; i += 256) sW2p[i] = prW2[i];
        if (tid < H2) { sW3p[tid] = prW3[tid]; sb2p[tid] = prb2[tid]; }
        __syncthreads();

        float lim = (float)(wk + 1);
        float h2[H2];
        #pragma unroll
        for (int m = 0; m < H2; m++) h2[m] = sb2p[m];
        #pragma unroll 4
        for (int j = 0; j < H1; j++) {
            float h1 = fmaxf(sYP[g * 32 + j] + lim * sr0[j], 0.f);
            #pragma unroll
            for (int m = 0; m < H2; m++) h2[m] += h1 * sW2p[j * H2 + m];
        }
        float lg = prb3[0];
        #pragma unroll
        for (int m = 0; m < H2; m++) lg += fmaxf(h2[m], 0.f) * sW3p[m];
        lg -= (1.f - pmsk[(size_t)dag * W + wk]) * 1000.f;

        red[g * 64 + wk] = lg;
        __syncthreads();
        for (int st = 32; st > 0; st >>= 1) {
            if (wk < st) red[g * 64 + wk] = fmaxf(red[g * 64 + wk], red[g * 64 + wk + st]);
            __syncthreads();
        }
        float mx = red[g * 64];
        __syncthreads();
        float ev = expf(lg - mx);
        red[g * 64 + wk] = ev;
        __syncthreads();
        for (int st = 32; st > 0; st >>= 1) {
            if (wk < st) red[g * 64 + wk] += red[g * 64 + wk + st];
            __syncthreads();
        }
        out_pr[(size_t)dag * W + wk] = ev / red[g * 64];
        return;
    }

    // ---------- op branch: 128 ops/block, 8 K-chunks of 32, 3-buffer pipeline ----------
    ull*    sw   = (ull*)(sm_raw + OP_SW);
    float4* sx   = (float4*)(sm_raw + OP_SX);
    float*  sH   = (float*)(sm_raw + OP_SH);
    float*  sW2  = (float*)(sm_raw + OP_SW2);
    float*  sW3  = (float*)(sm_raw + OP_SW3);
    float*  sb2  = (float*)(sm_raw + OP_SB2);
    float*  sRed = (float*)(sm_raw + OP_SRED);

    int base = blockIdx.x * 128;
    int warp = tid >> 5, lane = tid & 31;
    const float4* xg = (const float4*)x;

    // stage packed W1 + layer-2/3 weights
    {
        const float4* ws = (const float4*)g_wpk;
        float4* wd = (float4*)sw;
        #pragma unroll 4
        for (int i = tid; i < 2048; i += 256) wd[i] = ws[i];
    }
    for (int i = tid; i < H1 * H2; i += 256) sW2[i] = opW2[i];
    if (tid < H2) { sW3[tid] = opW3[tid]; sb2[tid] = opb2[tid]; }

    int op_s = (tid + 256 * 0) >> 3;   // staging op/col for r in 0..3
    float4 pf[4];
    // prefetch chunk 0
    #pragma unroll
    for (int r = 0; r < 4; r++) {
        int idx = tid + 256 * r;
        int op = idx >> 3, col = idx & 7;
        int gi = min(base + op, n - 1);
        pf[r] = xg[(size_t)gi * 64 + col];
    }
    #pragma unroll
    for (int r = 0; r < 4; r++) sx[tid + 256 * r] = pf[r];
    __syncthreads();
    (void)op_s;

    ull acc[16];
    #pragma unroll
    for (int u = 0; u < 16; u++) acc[u] = 0ull;

    const ulonglong2* wq = (const ulonglong2*)sw;
    for (int c = 0; c < 8; c++) {
        if (c < 7) {
            #pragma unroll
            for (int r = 0; r < 4; r++) {
                int idx = tid + 256 * r;
                int op = idx >> 3, col = idx & 7;
                int gi = min(base + op, n - 1);
                pf[r] = xg[(size_t)gi * 64 + (c + 1) * 8 + col];
            }
        }
        const ulonglong2* xq = (const ulonglong2*)(sx + (c % 3) * 1024) + warp * 16 * 8;
        #pragma unroll
        for (int k4 = 0; k4 < 8; k4++) {
            ulonglong2 w = wq[(c * 8 + k4) * 32 + lane];
            #pragma unroll
            for (int u = 0; u < 16; u++) {
                ulonglong2 xv = xq[u * 8 + k4];
                acc[u] = ffma2(xv.x, w.x, acc[u]);
                acc[u] = ffma2(xv.y, w.y, acc[u]);
            }
        }
        if (c < 7) {
            float4* dst = sx + ((c + 1) % 3) * 1024;
            #pragma unroll
            for (int r = 0; r < 4; r++) dst[tid + 256 * r] = pf[r];
            __syncthreads();
        }
    }

    // epilogue: add y+cz, relu, transpose via smem
    float* sHw = sH + warp * (16 * 33);
    {
        float czv = g_czop[lane];
        #pragma unroll
        for (int u = 0; u < 16; u++) {
            int i = min(base + warp * 16 + u, n - 1);
            float ypc = g_yop[g_dagids[i] * H1 + lane] + czv;
            sHw[u * 33 + lane] = fmaxf(unpack_sum(acc[u]) + ypc, 0.f);
        }
    }
    __syncwarp();

    // layers 2+3: lane -> (op o2 = lane>>1, neuron half m2 = lane&1)
    int o2 = lane >> 1, m2 = lane & 1;
    float h2[8];
    #pragma unroll
    for (int q = 0; q < 8; q++) h2[q] = sb2[m2 * 8 + q];
    const float* hrow = sHw + o2 * 33;
    #pragma unroll 8
    for (int j = 0; j < H1; j++) {
        float h = hrow[j];
        #pragma unroll
        for (int q = 0; q < 8; q++) h2[q] += h * sW2[j * H2 + m2 * 8 + q];
    }
    float part = 0.f;
    #pragma unroll
    for (int q = 0; q < 8; q++) part += fmaxf(h2[q], 0.f) * sW3[m2 * 8 + q];
    part += __shfl_xor_sync(0xffffffffu, part, 1);

    float e = 0.f;
    {
        int i = base + warp * 16 + o2;
        if (m2 == 0 && i < n) {
            float lg = part + opb3[0] - (1.f - omsk[i]) * 1000.f;
            e = expf(lg);
            out_ops[i] = e;
        }
    }
    e += __shfl_xor_sync(0xffffffffu, e, 1);
    e += __shfl_xor_sync(0xffffffffu, e, 2);
    e += __shfl_xor_sync(0xffffffffu, e, 4);
    e += __shfl_xor_sync(0xffffffffu, e, 8);
    e += __shfl_xor_sync(0xffffffffu, e, 16);
    if (lane == 0) sRed[warp] = e;
    __syncthreads();
    if (tid == 0) {
        float sum = 0.f;
        #pragma unroll
        for (int w = 0; w < 8; w++) sum += sRed[w];
        g_partials[blockIdx.x] = sum;
    }
}

// ---------------- K3: reduce partials + normalize (float4) ----------------
__global__ void __launch_bounds__(256)
k_norm(float* __restrict__ out_ops, int n, int nb_op)
{
    __shared__ float red[256];
    int t = threadIdx.x;
    float s = 0.f;
    for (int q = t; q < nb_op; q += 256) s += g_partials[q];
    red[t] = s;
    __syncthreads();
    for (int st = 128; st > 0; st >>= 1) {
        if (t < st) red[t] += red[t + st];
        __syncthreads();
    }
    float inv = 1.f / red[0];
    int n4 = n >> 2;
    float4* o4 = (float4*)out_ops;
    for (int i = blockIdx.x * 256 + t; i < n4; i += gridDim.x * 256) {
        float4 v = o4[i];
        v.x *= inv; v.y *= inv; v.z *= inv; v.w *= inv;
        o4[i] = v;
    }
    if (blockIdx.x == 0) {
        for (int i = (n & ~3) + t; i < n; i += 256) out_ops[i] *= inv;
    }
}

// ---------------- launch ----------------
extern "C" void kernel_launch(void* const* d_in, const int* in_sizes, int n_in,
                              void* d_out, int out_size)
{
    int ix = -1;
    for (int i = 0; i < n_in; i++) {
        if (in_sizes[i] == MAXN * E) { ix = i; break; }
    }
    if (ix < 0) return;

    const int*   num_ops = (const int*)d_in[0];
    int D = in_sizes[0];
    const float* x    = (const float*)d_in[ix + 0];
    const float* y    = (const float*)d_in[ix + 1];
    const float* z    = (const float*)d_in[ix + 2];
    const float* omsk = (const float*)d_in[ix + 3];
    const float* pmsk = (const float*)d_in[ix + 4];
    const float* opW1 = (const float*)d_in[ix + 5];
    const float* opb1 = (const float*)d_in[ix + 6];
    const float* opW2 = (const float*)d_in[ix + 7];
    const float* opb2 = (const float*)d_in[ix + 8];
    const float* opW3 = (const float*)d_in[ix + 9];
    const float* opb3 = (const float*)d_in[ix + 10];
    const float* prW1 = (const float*)d_in[ix + 11];
    const float* prb1 = (const float*)d_in[ix + 12];
    const float* prW2 = (const float*)d_in[ix + 13];
    const float* prb2 = (const float*)d_in[ix + 14];
    const float* prW3 = (const float*)d_in[ix + 15];
    const float* prb3 = (const float*)d_in[ix + 16];

    int n = in_sizes[ix] / E;
    int W = in_sizes[ix + 4] / D;
    int nb_op = (n + 127) / 128;
    float* out_ops = (float*)d_out;
    float* out_pr  = out_ops + n;
    (void)out_size;

    cudaFuncSetAttribute(k_op,  cudaFuncAttributeMaxDynamicSharedMemorySize, OP_TOTAL);
    cudaFuncSetAttribute(k_pre, cudaFuncAttributeMaxDynamicSharedMemorySize, PRE_SMEM);

    int grid_pre = D / 8 + D / 16 + 3;     // y-pre + dagfill + repack + 2 cz
    k_pre<<<grid_pre, 256, PRE_SMEM>>>(y, opW1, opb1, prW1, prb1, z, num_ops, D);
    k_op<<<nb_op + D / 4, 256, OP_TOTAL>>>(x, opW2, opb2, opW3, opb3, omsk, n, nb_op,
                                           prW1, prW2, prb2, prW3, prb3, pmsk,
                                           out_ops, out_pr, W);
    int n4b = ((n >> 2) + 255) / 256;
    if (n4b < 1) n4b = 1;
    if (n4b > 296) n4b = 296;
    k_norm<<<n4b, 256>>>(out_ops, n, nb_op);
}